// round 3
// baseline (speedup 1.0000x reference)
#include <cuda_runtime.h>

#define H 4096
#define W 4096
#define OH 4090
#define OW 4090

#define BX_TILE 128
#define BY_TILE 32
#define VP_ROWS 37      // vertical-pair rows: covers input rows 0..37 of the tile
#define VP_PITCH 136    // float2 elements per vp row (134 needed, padded)
#define FILL_C4 34      // float4-chunks of 4 vpairs per row: 34*4 = 136

typedef unsigned long long ull;

__device__ __forceinline__ void ffma2(ull &d, ull a, ull b) {
    asm("fma.rn.f32x2 %0, %1, %2, %3;" : "=l"(d) : "l"(a), "l"(b), "l"(d));
}
__device__ __forceinline__ void unpack2(ull v, float &lo, float &hi) {
    asm("mov.b64 {%0, %1}, %2;" : "=f"(lo), "=f"(hi) : "l"(v));
}

__global__ __launch_bounds__(256, 3)
void conv7x7_vp_kernel(const float* __restrict__ X,
                       const float* __restrict__ Wt,
                       const float* __restrict__ Bs,
                       float* __restrict__ out) {
    // vp[r][x] = (in[by+r][bx+x], in[by+r+1][bx+x])  -- vertical pair
    __shared__ float2 vp[VP_ROWS][VP_PITCH];
    __shared__ float2 w2[49];

    const int tid = threadIdx.x;
    const int bx = blockIdx.x * BX_TILE;
    const int by = blockIdx.y * BY_TILE;

    // Weight pairs (w, w) for lanewise FFMA2.
    if (tid < 49) { float w = Wt[tid]; w2[tid] = make_float2(w, w); }

    // Fill: each chunk loads float4 from two adjacent input rows and writes
    // 4 interleaved vertical pairs as 2x STS.128. Clamped OOB data only feeds
    // outputs that are predicated off in the epilogue.
    for (int idx = tid; idx < VP_ROWS * FILL_C4; idx += 256) {
        int r  = idx / FILL_C4;
        int c4 = idx - r * FILL_C4;
        int gyA = by + r;      if (gyA > H - 1) gyA = H - 1;
        int gyB = by + r + 1;  if (gyB > H - 1) gyB = H - 1;
        int gx  = bx + c4 * 4; if (gx > W - 4)  gx  = W - 4;
        float4 a = *reinterpret_cast<const float4*>(X + (size_t)gyA * W + gx);
        float4 b = *reinterpret_cast<const float4*>(X + (size_t)gyB * W + gx);
        float4* dst = reinterpret_cast<float4*>(&vp[r][c4 * 4]);
        dst[0] = make_float4(a.x, b.x, a.y, b.y);
        dst[1] = make_float4(a.z, b.z, a.w, b.w);
    }
    __syncthreads();

    const int lane = tid & 31;
    const int wy   = tid >> 5;
    const int ox0  = lane * 4;   // output col within tile (4 cols/thread)
    const int oy0  = wy * 4;     // output row within tile (4 rows/thread)

    // acc[pr][c] = f32x2 (out[oy0+2pr][ox0+c], out[oy0+2pr+1][ox0+c])
    ull acc[2][4];
#pragma unroll
    for (int pr = 0; pr < 2; pr++)
#pragma unroll
        for (int c = 0; c < 4; c++) acc[pr][c] = 0ull;

    const float2* vbase = &vp[oy0][ox0];

    // ky-outer: 7 weight pairs live in 14 registers; input pairs come straight
    // from aligned LDS.128 (no register packing).
#pragma unroll
    for (int ky = 0; ky < 7; ky++) {
        ull wk[7];
#pragma unroll
        for (int i = 0; i < 7; i++)
            wk[i] = *reinterpret_cast<const ull*>(&w2[ky * 7 + i]);
#pragma unroll
        for (int pr = 0; pr < 2; pr++) {
            const ulonglong2* qp =
                reinterpret_cast<const ulonglong2*>(vbase + (2 * pr + ky) * VP_PITCH);
            ull q[10];
#pragma unroll
            for (int j = 0; j < 5; j++) {
                ulonglong2 v = qp[j];
                q[2 * j]     = v.x;
                q[2 * j + 1] = v.y;
            }
#pragma unroll
            for (int kx = 0; kx < 7; kx++)
#pragma unroll
                for (int c = 0; c < 4; c++)
                    ffma2(acc[pr][c], q[c + kx], wk[kx]);
        }
    }

    const float bias = Bs[0];

#pragma unroll
    for (int pr = 0; pr < 2; pr++) {
        const int rA = by + oy0 + 2 * pr;  // always even -> 16B-aligned row base
        const int rB = rA + 1;             // always odd  -> 8B-aligned row base
        const int ocol = bx + ox0;
        float a[4], b[4];
#pragma unroll
        for (int c = 0; c < 4; c++) {
            unpack2(acc[pr][c], a[c], b[c]);
            a[c] += bias; b[c] += bias;
        }
        if (ocol + 3 < OW) {
            if (rA < OH)
                *reinterpret_cast<float4*>(out + (size_t)rA * OW + ocol) =
                    make_float4(a[0], a[1], a[2], a[3]);
            if (rB < OH) {
                float* p = out + (size_t)rB * OW + ocol;
                *reinterpret_cast<float2*>(p)     = make_float2(b[0], b[1]);
                *reinterpret_cast<float2*>(p + 2) = make_float2(b[2], b[3]);
            }
        } else {
#pragma unroll
            for (int c = 0; c < 4; c++) {
                if (ocol + c < OW) {
                    if (rA < OH) out[(size_t)rA * OW + ocol + c] = a[c];
                    if (rB < OH) out[(size_t)rB * OW + ocol + c] = b[c];
                }
            }
        }
    }
}

extern "C" void kernel_launch(void* const* d_in, const int* in_sizes, int n_in,
                              void* d_out, int out_size) {
    const float* X  = (const float*)d_in[0];
    const float* Wt = (const float*)d_in[1];
    const float* Bs = (const float*)d_in[2];
    float* out = (float*)d_out;
    dim3 grid((OW + BX_TILE - 1) / BX_TILE, (OH + BY_TILE - 1) / BY_TILE);
    conv7x7_vp_kernel<<<grid, 256>>>(X, Wt, Bs, out);
}